// round 9
// baseline (speedup 1.0000x reference)
#include <cuda_runtime.h>

#define BSZ 2048
#define LSZ 200
#define DSZ 256

// Scratch (device globals — no allocation allowed).
__device__ float g_M[DSZ * DSZ];     // M = W_query @ W_key^T
__device__ float g_QK[BSZ * DSZ];    // q @ M
__device__ float g_CTX[BSZ * DSZ];   // softmax-weighted sum of k rows

// ---------------------------------------------------------------------------
// g_M[i][j] = Wq[i,:] . Wk[j,:]
// grid = 256 CTAs (one per output row i), 8 warps, warp w covers 32 cols.
// ---------------------------------------------------------------------------
__global__ void wmat_kernel(const float* __restrict__ Wq,
                            const float* __restrict__ Wk)
{
    const int i = blockIdx.x;
    const int w = threadIdx.x >> 5;
    const int lane = threadIdx.x & 31;

    const float4* ap = (const float4*)(Wq + i * 256 + lane * 8);
    const float4 a0 = ap[0];
    const float4 a1 = ap[1];

    float res = 0.0f;
    #pragma unroll 4
    for (int jj = 0; jj < 32; jj++) {
        const int j = w * 32 + jj;
        const float4* bp = (const float4*)(Wk + j * 256 + lane * 8);
        const float4 b0 = __ldg(bp);
        const float4 b1 = __ldg(bp + 1);
        float d = a0.x * b0.x + a0.y * b0.y + a0.z * b0.z + a0.w * b0.w
                + a1.x * b1.x + a1.y * b1.y + a1.z * b1.z + a1.w * b1.w;
        #pragma unroll
        for (int off = 16; off > 0; off >>= 1)
            d += __shfl_xor_sync(0xffffffffu, d, off);
        if (lane == jj) res = d;
    }
    g_M[i * 256 + w * 32 + lane] = res;
}

// ---------------------------------------------------------------------------
// rowvec GEMM: C[16 rows] = A[16 rows, 256] @ B[256,256]
// grid = 128 CTAs (16 rows each), 256 threads; thread tid owns column tid
// with 16 row-accumulators. A staged TRANSPOSED in smem -> one LDS.128 x4
// broadcast per k-step; B column loads coalesced, L2-resident.
// No barrier in the mainloop; 16 independent FFMA per B-load.
// ---------------------------------------------------------------------------
#define RV_ROWS 16
#define RV_PAD  20   // row stride (floats): 80B keeps float4 alignment

__device__ __forceinline__ void rowvec_gemm_body(const float* __restrict__ A,
                                                 const float* __restrict__ B,
                                                 float* __restrict__ C)
{
    __shared__ float sAT[DSZ][RV_PAD];   // sAT[d][r] = A[row0+r][d]
    const int tid = threadIdx.x;
    const int row0 = blockIdx.x * RV_ROWS;

    #pragma unroll
    for (int r = 0; r < RV_ROWS; r++)
        sAT[tid][r] = __ldg(A + (size_t)(row0 + r) * DSZ + tid);
    __syncthreads();

    float acc[RV_ROWS] = {};
    const float* Bc = B + tid;
    #pragma unroll 4
    for (int d = 0; d < DSZ; d++) {
        const float bv = __ldg(Bc + (size_t)d * DSZ);
        const float4 a0 = *(const float4*)&sAT[d][0];
        const float4 a1 = *(const float4*)&sAT[d][4];
        const float4 a2 = *(const float4*)&sAT[d][8];
        const float4 a3 = *(const float4*)&sAT[d][12];
        acc[0]  += a0.x * bv; acc[1]  += a0.y * bv;
        acc[2]  += a0.z * bv; acc[3]  += a0.w * bv;
        acc[4]  += a1.x * bv; acc[5]  += a1.y * bv;
        acc[6]  += a1.z * bv; acc[7]  += a1.w * bv;
        acc[8]  += a2.x * bv; acc[9]  += a2.y * bv;
        acc[10] += a2.z * bv; acc[11] += a2.w * bv;
        acc[12] += a3.x * bv; acc[13] += a3.y * bv;
        acc[14] += a3.z * bv; acc[15] += a3.w * bv;
    }
    #pragma unroll
    for (int r = 0; r < RV_ROWS; r++)
        C[(size_t)(row0 + r) * DSZ + tid] = acc[r];
}

// QK = q @ g_M
__global__ void __launch_bounds__(256)
qk_gemm_kernel(const float* __restrict__ q)
{
    rowvec_gemm_body(q, g_M, g_QK);
}

// out = g_CTX @ Wv
__global__ void __launch_bounds__(256)
out_gemm_kernel(const float* __restrict__ Wv,
                float* __restrict__ out)
{
    rowvec_gemm_body(g_CTX, Wv, out);
}

// ---------------------------------------------------------------------------
// Attention in k-space. One CTA per batch (grid 2048, ~3.5 waves -> HW
// load-balancing over variable len). Reads ONLY the first nrows rows:
// masked rows have p == exp(PAD/16 - 1/16) == +0.0f exactly -> contribute
// nothing to Z or CTX, so they are skipped. len==0 -> all-PAD -> uniform
// weights (p=1) over all 200 rows. Fixed-max softmax is exact (valid logits
// = sigmoid/16 in (0, 1/16]).
// Mainloop: 3 rows per outer step -> 6 LDG.128 in flight per warp.
// ---------------------------------------------------------------------------
__global__ void __launch_bounds__(256, 4)
attn_kernel(const float* __restrict__ K,
            const int* __restrict__ keys_length,
            const float* __restrict__ bias)
{
    __shared__ float sZ[8];
    __shared__ float sctx[8][DSZ];

    const int tid = threadIdx.x;
    const int w = tid >> 5;
    const int lane = tid & 31;
    const int b = blockIdx.x;

    const float* kb = K + (size_t)b * LSZ * DSZ;
    const float4* qkp = (const float4*)(g_QK + (size_t)b * DSZ + lane * 8);
    const float4 q0 = qkp[0];
    const float4 q1 = qkp[1];

    const int len = keys_length[b];
    const bool uniform = (len == 0);
    const int nrows = uniform ? LSZ : len;
    const float b256 = bias[0] * 256.0f;

    // warp w owns rows l = w, w+8, w+16, ...
    const int nit = (nrows > w) ? ((nrows - w + 7) >> 3) : 0;
    const float* rp = kb + (size_t)w * DSZ + lane * 8;
    const size_t rstep = (size_t)8 * DSZ;

    float Z = 0.0f;
    float c0 = 0.f, c1 = 0.f, c2 = 0.f, c3 = 0.f;
    float c4 = 0.f, c5 = 0.f, c6 = 0.f, c7 = 0.f;

    int i = 0;
    #pragma unroll 1
    for (; i + 3 <= nit; i += 3) {
        // issue all 6 loads before any reduce chain
        const float4 x0 = __ldg((const float4*)rp);
        const float4 y0 = __ldg((const float4*)rp + 1);
        const float4 x1 = __ldg((const float4*)(rp + rstep));
        const float4 y1 = __ldg((const float4*)(rp + rstep) + 1);
        const float4 x2 = __ldg((const float4*)(rp + 2 * rstep));
        const float4 y2 = __ldg((const float4*)(rp + 2 * rstep) + 1);
        rp += 3 * rstep;

        float d0 = x0.x * q0.x + x0.y * q0.y + x0.z * q0.z + x0.w * q0.w
                 + y0.x * q1.x + y0.y * q1.y + y0.z * q1.z + y0.w * q1.w;
        float d1 = x1.x * q0.x + x1.y * q0.y + x1.z * q0.z + x1.w * q0.w
                 + y1.x * q1.x + y1.y * q1.y + y1.z * q1.z + y1.w * q1.w;
        float d2 = x2.x * q0.x + x2.y * q0.y + x2.z * q0.z + x2.w * q0.w
                 + y2.x * q1.x + y2.y * q1.y + y2.z * q1.z + y2.w * q1.w;
        #pragma unroll
        for (int off = 16; off > 0; off >>= 1) {
            d0 += __shfl_xor_sync(0xffffffffu, d0, off);
            d1 += __shfl_xor_sync(0xffffffffu, d1, off);
            d2 += __shfl_xor_sync(0xffffffffu, d2, off);
        }

        float p0, p1, p2;
        if (uniform) {
            p0 = p1 = p2 = 1.0f;
        } else {
            const float s0 = 1.0f / (1.0f + __expf(-(d0 + b256)));
            const float s1 = 1.0f / (1.0f + __expf(-(d1 + b256)));
            const float s2 = 1.0f / (1.0f + __expf(-(d2 + b256)));
            p0 = __expf(s0 * 0.0625f - 0.0625f);
            p1 = __expf(s1 * 0.0625f - 0.0625f);
            p2 = __expf(s2 * 0.0625f - 0.0625f);
        }

        Z += p0 + p1 + p2;
        c0 += p0 * x0.x + p1 * x1.x + p2 * x2.x;
        c1 += p0 * x0.y + p1 * x1.y + p2 * x2.y;
        c2 += p0 * x0.z + p1 * x1.z + p2 * x2.z;
        c3 += p0 * x0.w + p1 * x1.w + p2 * x2.w;
        c4 += p0 * y0.x + p1 * y1.x + p2 * y2.x;
        c5 += p0 * y0.y + p1 * y1.y + p2 * y2.y;
        c6 += p0 * y0.z + p1 * y1.z + p2 * y2.z;
        c7 += p0 * y0.w + p1 * y1.w + p2 * y2.w;
    }
    #pragma unroll 1
    for (; i < nit; i++) {
        const float4 x0 = __ldg((const float4*)rp);
        const float4 y0 = __ldg((const float4*)rp + 1);
        rp += rstep;
        float d0 = x0.x * q0.x + x0.y * q0.y + x0.z * q0.z + x0.w * q0.w
                 + y0.x * q1.x + y0.y * q1.y + y0.z * q1.z + y0.w * q1.w;
        #pragma unroll
        for (int off = 16; off > 0; off >>= 1)
            d0 += __shfl_xor_sync(0xffffffffu, d0, off);
        float p0;
        if (uniform) {
            p0 = 1.0f;
        } else {
            const float s0 = 1.0f / (1.0f + __expf(-(d0 + b256)));
            p0 = __expf(s0 * 0.0625f - 0.0625f);
        }
        Z += p0;
        c0 += p0 * x0.x; c1 += p0 * x0.y; c2 += p0 * x0.z; c3 += p0 * x0.w;
        c4 += p0 * y0.x; c5 += p0 * y0.y; c6 += p0 * y0.z; c7 += p0 * y0.w;
    }

    if (lane == 0) sZ[w] = Z;   // Z identical across lanes after butterfly
    const int d = lane * 8;
    sctx[w][d + 0] = c0; sctx[w][d + 1] = c1;
    sctx[w][d + 2] = c2; sctx[w][d + 3] = c3;
    sctx[w][d + 4] = c4; sctx[w][d + 5] = c5;
    sctx[w][d + 6] = c6; sctx[w][d + 7] = c7;
    __syncthreads();

    float zt = 0.0f;
    #pragma unroll
    for (int ww = 0; ww < 8; ww++) zt += sZ[ww];
    float c = 0.0f;
    #pragma unroll
    for (int ww = 0; ww < 8; ww++) c += sctx[ww][tid];

    g_CTX[(size_t)b * DSZ + tid] = c / zt;
}

// ---------------------------------------------------------------------------
extern "C" void kernel_launch(void* const* d_in, const int* in_sizes, int n_in,
                              void* d_out, int out_size)
{
    const float* q      = (const float*)d_in[0];   // [2048, 1, 256]
    const float* k      = (const float*)d_in[1];   // [2048, 200, 256]
    // d_in[2] = v: unused (reference derives both score and value paths from k)
    const int*   klen   = (const int*)d_in[3];     // [2048, 1]
    const float* Wq     = (const float*)d_in[4];   // [256, 256]
    const float* Wk     = (const float*)d_in[5];   // [256, 256]
    const float* Wv     = (const float*)d_in[6];   // [256, 256]
    const float* bias   = (const float*)d_in[7];   // [1]
    float* out = (float*)d_out;                    // [2048, 1, 256]

    // 1) M = Wq @ Wk^T
    wmat_kernel<<<256, 256>>>(Wq, Wk);
    // 2) QK = q @ M
    qk_gemm_kernel<<<BSZ / RV_ROWS, 256>>>(q);
    // 3) attention in k-space (reads only valid rows)
    attn_kernel<<<BSZ, 256>>>(k, klen, bias);
    // 4) out = CTX @ Wv
    out_gemm_kernel<<<BSZ / RV_ROWS, 256>>>(Wv, out);
}

// round 11
// speedup vs baseline: 1.3102x; 1.3102x over previous
#include <cuda_runtime.h>

#define BSZ 2048
#define LSZ 200
#define DSZ 256

// Scratch (device globals — no allocation allowed).
__device__ float g_M[DSZ * DSZ];     // M = W_query @ W_key^T
__device__ float g_QK[BSZ * DSZ];    // q @ M
__device__ float g_CTX[BSZ * DSZ];   // softmax-weighted sum of k rows

// ---------------------------------------------------------------------------
// g_M[i][j] = Wq[i,:] . Wk[j,:]
// grid = 256 CTAs (one per output row i), 8 warps, warp w covers 32 cols.
// ---------------------------------------------------------------------------
__global__ void wmat_kernel(const float* __restrict__ Wq,
                            const float* __restrict__ Wk)
{
    const int i = blockIdx.x;
    const int w = threadIdx.x >> 5;
    const int lane = threadIdx.x & 31;

    const float4* ap = (const float4*)(Wq + i * 256 + lane * 8);
    const float4 a0 = ap[0];
    const float4 a1 = ap[1];

    float res = 0.0f;
    #pragma unroll 4
    for (int jj = 0; jj < 32; jj++) {
        const int j = w * 32 + jj;
        const float4* bp = (const float4*)(Wk + j * 256 + lane * 8);
        const float4 b0 = __ldg(bp);
        const float4 b1 = __ldg(bp + 1);
        float d = a0.x * b0.x + a0.y * b0.y + a0.z * b0.z + a0.w * b0.w
                + a1.x * b1.x + a1.y * b1.y + a1.z * b1.z + a1.w * b1.w;
        #pragma unroll
        for (int off = 16; off > 0; off >>= 1)
            d += __shfl_xor_sync(0xffffffffu, d, off);
        if (lane == jj) res = d;
    }
    g_M[i * 256 + w * 32 + lane] = res;
}

// ---------------------------------------------------------------------------
// Double-buffered tiled GEMM: C[2048,256] = A[2048,256] @ B[256,256]
// BM=BN=32, BK=32, 128 threads, grid (64,8)=512 CTAs (~3.5/SM).
// Per chunk: issue 4 global float4 loads -> compute current smem buffer
// (covers L2 latency) -> store regs into the other buffer -> ONE barrier.
// Per thread per kk-step: LDS.128 + LDS.64 + 8 FFMA (76% FFMA issue mix).
// ---------------------------------------------------------------------------
#define GM_BM 32
#define GM_BN 32
#define GM_BK 32
#define GM_PAD 36   // As row stride in floats (144B: keeps 16B alignment)

__device__ __forceinline__ void tgemm_body(const float* __restrict__ A,
                                           const float* __restrict__ B,
                                           float* __restrict__ C)
{
    __shared__ float As[2][GM_BK][GM_PAD];   // [k][m]
    __shared__ float Bs[2][GM_BK][GM_BN];    // [k][n]

    const int tid = threadIdx.x;
    const int row0 = blockIdx.x * GM_BM;
    const int col0 = blockIdx.y * GM_BN;

    // global load mapping
    const int ar = tid >> 2;              // 0..31 (A row)
    const int ak = (tid & 3) * 4;         // 0,4,8,12 (A k-offset, float4)
    const int bk = tid >> 3;              // 0..15 (B k)
    const int bc = (tid & 7) * 4;         // 0..28 (B col, float4)

    const float* Ap = A + (size_t)(row0 + ar) * DSZ + ak;
    const float* Bp = B + (size_t)bk * DSZ + col0 + bc;

    // compute mapping: 4 rows x 2 cols per thread
    const int ty = tid >> 4;              // 0..7 -> rows ty*4..ty*4+3
    const int tx = tid & 15;              // cols tx*2, tx*2+1

    float acc[4][2] = {};

    // ---- preload chunk 0 into buffer 0
    float4 a0 = __ldg((const float4*)Ap);
    float4 a1 = __ldg((const float4*)(Ap + 16));
    float4 b0 = __ldg((const float4*)Bp);
    float4 b1 = __ldg((const float4*)(Bp + (size_t)16 * DSZ));

    As[0][ak + 0][ar] = a0.x; As[0][ak + 1][ar] = a0.y;
    As[0][ak + 2][ar] = a0.z; As[0][ak + 3][ar] = a0.w;
    As[0][ak + 16][ar] = a1.x; As[0][ak + 17][ar] = a1.y;
    As[0][ak + 18][ar] = a1.z; As[0][ak + 19][ar] = a1.w;
    *(float4*)&Bs[0][bk][bc] = b0;
    *(float4*)&Bs[0][bk + 16][bc] = b1;
    __syncthreads();

    int buf = 0;
    #pragma unroll 1
    for (int c = 0; c < DSZ / GM_BK; c++) {
        const bool more = (c + 1 < DSZ / GM_BK);
        if (more) {
            const float* Ap2 = Ap + (c + 1) * GM_BK;
            const float* Bp2 = Bp + (size_t)(c + 1) * GM_BK * DSZ;
            a0 = __ldg((const float4*)Ap2);
            a1 = __ldg((const float4*)(Ap2 + 16));
            b0 = __ldg((const float4*)Bp2);
            b1 = __ldg((const float4*)(Bp2 + (size_t)16 * DSZ));
        }

        #pragma unroll
        for (int kk = 0; kk < GM_BK; kk++) {
            const float4 av = *(const float4*)&As[buf][kk][ty * 4];
            const float2 bv = *(const float2*)&Bs[buf][kk][tx * 2];
            acc[0][0] += av.x * bv.x; acc[0][1] += av.x * bv.y;
            acc[1][0] += av.y * bv.x; acc[1][1] += av.y * bv.y;
            acc[2][0] += av.z * bv.x; acc[2][1] += av.z * bv.y;
            acc[3][0] += av.w * bv.x; acc[3][1] += av.w * bv.y;
        }

        if (more) {
            const int nb = buf ^ 1;       // freed by the previous barrier
            As[nb][ak + 0][ar] = a0.x; As[nb][ak + 1][ar] = a0.y;
            As[nb][ak + 2][ar] = a0.z; As[nb][ak + 3][ar] = a0.w;
            As[nb][ak + 16][ar] = a1.x; As[nb][ak + 17][ar] = a1.y;
            As[nb][ak + 18][ar] = a1.z; As[nb][ak + 19][ar] = a1.w;
            *(float4*)&Bs[nb][bk][bc] = b0;
            *(float4*)&Bs[nb][bk + 16][bc] = b1;
        }
        __syncthreads();
        buf ^= 1;
    }

    #pragma unroll
    for (int i = 0; i < 4; i++) {
        float2 v; v.x = acc[i][0]; v.y = acc[i][1];
        *(float2*)(C + (size_t)(row0 + ty * 4 + i) * DSZ + col0 + tx * 2) = v;
    }
}

// QK = q @ g_M
__global__ void __launch_bounds__(128)
qk_gemm_kernel(const float* __restrict__ q)
{
    tgemm_body(q, g_M, g_QK);
}

// out = g_CTX @ Wv
__global__ void __launch_bounds__(128)
out_gemm_kernel(const float* __restrict__ Wv,
                float* __restrict__ out)
{
    tgemm_body(g_CTX, Wv, out);
}

// ---------------------------------------------------------------------------
// Attention in k-space. One CTA per batch (grid 2048, ~3.5 waves -> HW
// load-balancing over variable len). Reads ONLY the first nrows rows:
// masked rows have p == exp(PAD/16 - 1/16) == +0.0f exactly -> contribute
// nothing to Z or CTX. len==0 -> all-PAD -> uniform weights over 200 rows.
// Fixed-max softmax is exact (valid logits = sigmoid/16 in (0, 1/16]).
// Mainloop: 3 rows per outer step -> 6 LDG.128 in flight per warp.
// ---------------------------------------------------------------------------
__global__ void __launch_bounds__(256, 4)
attn_kernel(const float* __restrict__ K,
            const int* __restrict__ keys_length,
            const float* __restrict__ bias)
{
    __shared__ float sZ[8];
    __shared__ float sctx[8][DSZ];

    const int tid = threadIdx.x;
    const int w = tid >> 5;
    const int lane = tid & 31;
    const int b = blockIdx.x;

    const float* kb = K + (size_t)b * LSZ * DSZ;
    const float4* qkp = (const float4*)(g_QK + (size_t)b * DSZ + lane * 8);
    const float4 q0 = qkp[0];
    const float4 q1 = qkp[1];

    const int len = keys_length[b];
    const bool uniform = (len == 0);
    const int nrows = uniform ? LSZ : len;
    const float b256 = bias[0] * 256.0f;

    // warp w owns rows l = w, w+8, w+16, ...
    const int nit = (nrows > w) ? ((nrows - w + 7) >> 3) : 0;
    const float* rp = kb + (size_t)w * DSZ + lane * 8;
    const size_t rstep = (size_t)8 * DSZ;

    float Z = 0.0f;
    float c0 = 0.f, c1 = 0.f, c2 = 0.f, c3 = 0.f;
    float c4 = 0.f, c5 = 0.f, c6 = 0.f, c7 = 0.f;

    int i = 0;
    #pragma unroll 1
    for (; i + 3 <= nit; i += 3) {
        const float4 x0 = __ldg((const float4*)rp);
        const float4 y0 = __ldg((const float4*)rp + 1);
        const float4 x1 = __ldg((const float4*)(rp + rstep));
        const float4 y1 = __ldg((const float4*)(rp + rstep) + 1);
        const float4 x2 = __ldg((const float4*)(rp + 2 * rstep));
        const float4 y2 = __ldg((const float4*)(rp + 2 * rstep) + 1);
        rp += 3 * rstep;

        float d0 = x0.x * q0.x + x0.y * q0.y + x0.z * q0.z + x0.w * q0.w
                 + y0.x * q1.x + y0.y * q1.y + y0.z * q1.z + y0.w * q1.w;
        float d1 = x1.x * q0.x + x1.y * q0.y + x1.z * q0.z + x1.w * q0.w
                 + y1.x * q1.x + y1.y * q1.y + y1.z * q1.z + y1.w * q1.w;
        float d2 = x2.x * q0.x + x2.y * q0.y + x2.z * q0.z + x2.w * q0.w
                 + y2.x * q1.x + y2.y * q1.y + y2.z * q1.z + y2.w * q1.w;
        #pragma unroll
        for (int off = 16; off > 0; off >>= 1) {
            d0 += __shfl_xor_sync(0xffffffffu, d0, off);
            d1 += __shfl_xor_sync(0xffffffffu, d1, off);
            d2 += __shfl_xor_sync(0xffffffffu, d2, off);
        }

        float p0, p1, p2;
        if (uniform) {
            p0 = p1 = p2 = 1.0f;
        } else {
            const float s0 = 1.0f / (1.0f + __expf(-(d0 + b256)));
            const float s1 = 1.0f / (1.0f + __expf(-(d1 + b256)));
            const float s2 = 1.0f / (1.0f + __expf(-(d2 + b256)));
            p0 = __expf(s0 * 0.0625f - 0.0625f);
            p1 = __expf(s1 * 0.0625f - 0.0625f);
            p2 = __expf(s2 * 0.0625f - 0.0625f);
        }

        Z += p0 + p1 + p2;
        c0 += p0 * x0.x + p1 * x1.x + p2 * x2.x;
        c1 += p0 * x0.y + p1 * x1.y + p2 * x2.y;
        c2 += p0 * x0.z + p1 * x1.z + p2 * x2.z;
        c3 += p0 * x0.w + p1 * x1.w + p2 * x2.w;
        c4 += p0 * y0.x + p1 * y1.x + p2 * y2.x;
        c5 += p0 * y0.y + p1 * y1.y + p2 * y2.y;
        c6 += p0 * y0.z + p1 * y1.z + p2 * y2.z;
        c7 += p0 * y0.w + p1 * y1.w + p2 * y2.w;
    }
    #pragma unroll 1
    for (; i < nit; i++) {
        const float4 x0 = __ldg((const float4*)rp);
        const float4 y0 = __ldg((const float4*)rp + 1);
        rp += rstep;
        float d0 = x0.x * q0.x + x0.y * q0.y + x0.z * q0.z + x0.w * q0.w
                 + y0.x * q1.x + y0.y * q1.y + y0.z * q1.z + y0.w * q1.w;
        #pragma unroll
        for (int off = 16; off > 0; off >>= 1)
            d0 += __shfl_xor_sync(0xffffffffu, d0, off);
        float p0;
        if (uniform) {
            p0 = 1.0f;
        } else {
            const float s0 = 1.0f / (1.0f + __expf(-(d0 + b256)));
            p0 = __expf(s0 * 0.0625f - 0.0625f);
        }
        Z += p0;
        c0 += p0 * x0.x; c1 += p0 * x0.y; c2 += p0 * x0.z; c3 += p0 * x0.w;
        c4 += p0 * y0.x; c5 += p0 * y0.y; c6 += p0 * y0.z; c7 += p0 * y0.w;
    }

    if (lane == 0) sZ[w] = Z;   // Z identical across lanes after butterfly
    const int d = lane * 8;
    sctx[w][d + 0] = c0; sctx[w][d + 1] = c1;
    sctx[w][d + 2] = c2; sctx[w][d + 3] = c3;
    sctx[w][d + 4] = c4; sctx[w][d + 5] = c5;
    sctx[w][d + 6] = c6; sctx[w][d + 7] = c7;
    __syncthreads();

    float zt = 0.0f;
    #pragma unroll
    for (int ww = 0; ww < 8; ww++) zt += sZ[ww];
    float c = 0.0f;
    #pragma unroll
    for (int ww = 0; ww < 8; ww++) c += sctx[ww][tid];

    g_CTX[(size_t)b * DSZ + tid] = c / zt;
}

// ---------------------------------------------------------------------------
extern "C" void kernel_launch(void* const* d_in, const int* in_sizes, int n_in,
                              void* d_out, int out_size)
{
    const float* q      = (const float*)d_in[0];   // [2048, 1, 256]
    const float* k      = (const float*)d_in[1];   // [2048, 200, 256]
    // d_in[2] = v: unused (reference derives both score and value paths from k)
    const int*   klen   = (const int*)d_in[3];     // [2048, 1]
    const float* Wq     = (const float*)d_in[4];   // [256, 256]
    const float* Wk     = (const float*)d_in[5];   // [256, 256]
    const float* Wv     = (const float*)d_in[6];   // [256, 256]
    const float* bias   = (const float*)d_in[7];   // [1]
    float* out = (float*)d_out;                    // [2048, 1, 256]

    // 1) M = Wq @ Wk^T
    wmat_kernel<<<256, 256>>>(Wq, Wk);
    // 2) QK = q @ M
    qk_gemm_kernel<<<dim3(BSZ / GM_BM, DSZ / GM_BN), 128>>>(q);
    // 3) attention in k-space (reads only valid rows)
    attn_kernel<<<BSZ, 256>>>(k, klen, bias);
    // 4) out = CTX @ Wv
    out_gemm_kernel<<<dim3(BSZ / GM_BM, DSZ / GM_BN), 128>>>(Wv, out);
}

// round 12
// speedup vs baseline: 1.4152x; 1.0802x over previous
#include <cuda_runtime.h>

#define BSZ 2048
#define LSZ 200
#define DSZ 256

// Scratch (device globals — no allocation allowed).
__device__ float g_M[DSZ * DSZ];     // M = W_query @ W_key^T
__device__ float g_QK[BSZ * DSZ];    // q @ M
__device__ float g_CTX[BSZ * DSZ];   // softmax-weighted sum of k rows

// ---------------------------------------------------------------------------
// g_M[i][j] = Wq[i,:] . Wk[j,:]
// grid = 256 CTAs (one per output row i), 8 warps, warp w covers 32 cols.
// ---------------------------------------------------------------------------
__global__ void wmat_kernel(const float* __restrict__ Wq,
                            const float* __restrict__ Wk)
{
    const int i = blockIdx.x;
    const int w = threadIdx.x >> 5;
    const int lane = threadIdx.x & 31;

    const float4* ap = (const float4*)(Wq + i * 256 + lane * 8);
    const float4 a0 = ap[0];
    const float4 a1 = ap[1];

    float res = 0.0f;
    #pragma unroll 4
    for (int jj = 0; jj < 32; jj++) {
        const int j = w * 32 + jj;
        const float4* bp = (const float4*)(Wk + j * 256 + lane * 8);
        const float4 b0 = __ldg(bp);
        const float4 b1 = __ldg(bp + 1);
        float d = a0.x * b0.x + a0.y * b0.y + a0.z * b0.z + a0.w * b0.w
                + a1.x * b1.x + a1.y * b1.y + a1.z * b1.z + a1.w * b1.w;
        #pragma unroll
        for (int off = 16; off > 0; off >>= 1)
            d += __shfl_xor_sync(0xffffffffu, d, off);
        if (lane == jj) res = d;
    }
    g_M[i * 256 + w * 32 + lane] = res;
}

// ---------------------------------------------------------------------------
// Double-buffered tiled GEMM: C[2048,256] = A[2048,256] @ B[256,256]
// BM=32, BN=64, BK=32, 128 threads, grid (64,4)=256 CTAs.
// Micro-tile 4x4: per kk-step LDS.128(A bcast) + LDS.128(B) = 32B per
// 16 FFMA (2 B/FMA) -> smem crossbar (128 B/cyc) sustains full FFMA rate.
// Per chunk: issue next chunk's 6 global float4 loads -> compute current
// buffer (32 kk-steps) -> store regs to other buffer -> ONE barrier.
// ---------------------------------------------------------------------------
#define GM_BM 32
#define GM_BN 64
#define GM_BK 32
#define GM_PAD 36   // As row stride in floats (144B: keeps 16B alignment)

__device__ __forceinline__ void tgemm_body(const float* __restrict__ A,
                                           const float* __restrict__ B,
                                           float* __restrict__ C)
{
    __shared__ float As[2][GM_BK][GM_PAD];   // [k][m], transposed
    __shared__ float Bs[2][GM_BK][GM_BN];    // [k][n]

    const int tid = threadIdx.x;
    const int row0 = blockIdx.x * GM_BM;
    const int col0 = blockIdx.y * GM_BN;

    // global load mapping
    const int ar = tid >> 2;              // 0..31 (A row)
    const int ak = (tid & 3) * 4;         // 0,4,8,12 (A k-offset, float4)
    const int bk = tid >> 4;              // 0..7  (B k base)
    const int bc = (tid & 15) * 4;        // 0..60 (B col, float4)

    const float* Ap = A + (size_t)(row0 + ar) * DSZ + ak;
    const float* Bp = B + (size_t)bk * DSZ + col0 + bc;

    // compute mapping: 4 rows x 4 cols per thread
    const int ty = tid >> 4;              // 0..7  -> rows ty*4..ty*4+3
    const int tx = tid & 15;              // 0..15 -> cols tx*4..tx*4+3

    float4 acc0 = {0.f,0.f,0.f,0.f};
    float4 acc1 = {0.f,0.f,0.f,0.f};
    float4 acc2 = {0.f,0.f,0.f,0.f};
    float4 acc3 = {0.f,0.f,0.f,0.f};

    // ---- preload chunk 0 into buffer 0
    float4 a0 = __ldg((const float4*)Ap);
    float4 a1 = __ldg((const float4*)(Ap + 16));
    float4 b0 = __ldg((const float4*)Bp);
    float4 b1 = __ldg((const float4*)(Bp + (size_t)8  * DSZ));
    float4 b2 = __ldg((const float4*)(Bp + (size_t)16 * DSZ));
    float4 b3 = __ldg((const float4*)(Bp + (size_t)24 * DSZ));

    As[0][ak + 0][ar] = a0.x; As[0][ak + 1][ar] = a0.y;
    As[0][ak + 2][ar] = a0.z; As[0][ak + 3][ar] = a0.w;
    As[0][ak + 16][ar] = a1.x; As[0][ak + 17][ar] = a1.y;
    As[0][ak + 18][ar] = a1.z; As[0][ak + 19][ar] = a1.w;
    *(float4*)&Bs[0][bk][bc]      = b0;
    *(float4*)&Bs[0][bk + 8][bc]  = b1;
    *(float4*)&Bs[0][bk + 16][bc] = b2;
    *(float4*)&Bs[0][bk + 24][bc] = b3;
    __syncthreads();

    int buf = 0;
    #pragma unroll 1
    for (int c = 0; c < DSZ / GM_BK; c++) {
        const bool more = (c + 1 < DSZ / GM_BK);
        if (more) {
            const float* Ap2 = Ap + (c + 1) * GM_BK;
            const float* Bp2 = Bp + (size_t)(c + 1) * GM_BK * DSZ;
            a0 = __ldg((const float4*)Ap2);
            a1 = __ldg((const float4*)(Ap2 + 16));
            b0 = __ldg((const float4*)Bp2);
            b1 = __ldg((const float4*)(Bp2 + (size_t)8  * DSZ));
            b2 = __ldg((const float4*)(Bp2 + (size_t)16 * DSZ));
            b3 = __ldg((const float4*)(Bp2 + (size_t)24 * DSZ));
        }

        #pragma unroll
        for (int kk = 0; kk < GM_BK; kk++) {
            const float4 av = *(const float4*)&As[buf][kk][ty * 4];
            const float4 bv = *(const float4*)&Bs[buf][kk][tx * 4];
            acc0.x += av.x * bv.x; acc0.y += av.x * bv.y;
            acc0.z += av.x * bv.z; acc0.w += av.x * bv.w;
            acc1.x += av.y * bv.x; acc1.y += av.y * bv.y;
            acc1.z += av.y * bv.z; acc1.w += av.y * bv.w;
            acc2.x += av.z * bv.x; acc2.y += av.z * bv.y;
            acc2.z += av.z * bv.z; acc2.w += av.z * bv.w;
            acc3.x += av.w * bv.x; acc3.y += av.w * bv.y;
            acc3.z += av.w * bv.z; acc3.w += av.w * bv.w;
        }

        if (more) {
            const int nb = buf ^ 1;       // freed by the previous barrier
            As[nb][ak + 0][ar] = a0.x; As[nb][ak + 1][ar] = a0.y;
            As[nb][ak + 2][ar] = a0.z; As[nb][ak + 3][ar] = a0.w;
            As[nb][ak + 16][ar] = a1.x; As[nb][ak + 17][ar] = a1.y;
            As[nb][ak + 18][ar] = a1.z; As[nb][ak + 19][ar] = a1.w;
            *(float4*)&Bs[nb][bk][bc]      = b0;
            *(float4*)&Bs[nb][bk + 8][bc]  = b1;
            *(float4*)&Bs[nb][bk + 16][bc] = b2;
            *(float4*)&Bs[nb][bk + 24][bc] = b3;
        }
        __syncthreads();
        buf ^= 1;
    }

    float* Cp = C + (size_t)(row0 + ty * 4) * DSZ + col0 + tx * 4;
    *(float4*)(Cp)            = acc0;
    *(float4*)(Cp + DSZ)      = acc1;
    *(float4*)(Cp + 2 * DSZ)  = acc2;
    *(float4*)(Cp + 3 * DSZ)  = acc3;
}

// QK = q @ g_M
__global__ void __launch_bounds__(128)
qk_gemm_kernel(const float* __restrict__ q)
{
    tgemm_body(q, g_M, g_QK);
}

// out = g_CTX @ Wv
__global__ void __launch_bounds__(128)
out_gemm_kernel(const float* __restrict__ Wv,
                float* __restrict__ out)
{
    tgemm_body(g_CTX, Wv, out);
}

// ---------------------------------------------------------------------------
// Attention in k-space. One CTA per batch (grid 2048, ~3.5 waves -> HW
// load-balancing over variable len). Reads ONLY the first nrows rows:
// masked rows have p == exp(PAD/16 - 1/16) == +0.0f exactly -> contribute
// nothing to Z or CTX. len==0 -> all-PAD -> uniform weights over 200 rows.
// Fixed-max softmax is exact (valid logits = sigmoid/16 in (0, 1/16]).
// Mainloop: 3 rows per outer step -> 6 LDG.128 in flight per warp.
// ---------------------------------------------------------------------------
__global__ void __launch_bounds__(256, 4)
attn_kernel(const float* __restrict__ K,
            const int* __restrict__ keys_length,
            const float* __restrict__ bias)
{
    __shared__ float sZ[8];
    __shared__ float sctx[8][DSZ];

    const int tid = threadIdx.x;
    const int w = tid >> 5;
    const int lane = tid & 31;
    const int b = blockIdx.x;

    const float* kb = K + (size_t)b * LSZ * DSZ;
    const float4* qkp = (const float4*)(g_QK + (size_t)b * DSZ + lane * 8);
    const float4 q0 = qkp[0];
    const float4 q1 = qkp[1];

    const int len = keys_length[b];
    const bool uniform = (len == 0);
    const int nrows = uniform ? LSZ : len;
    const float b256 = bias[0] * 256.0f;

    // warp w owns rows l = w, w+8, w+16, ...
    const int nit = (nrows > w) ? ((nrows - w + 7) >> 3) : 0;
    const float* rp = kb + (size_t)w * DSZ + lane * 8;
    const size_t rstep = (size_t)8 * DSZ;

    float Z = 0.0f;
    float c0 = 0.f, c1 = 0.f, c2 = 0.f, c3 = 0.f;
    float c4 = 0.f, c5 = 0.f, c6 = 0.f, c7 = 0.f;

    int i = 0;
    #pragma unroll 1
    for (; i + 3 <= nit; i += 3) {
        const float4 x0 = __ldg((const float4*)rp);
        const float4 y0 = __ldg((const float4*)rp + 1);
        const float4 x1 = __ldg((const float4*)(rp + rstep));
        const float4 y1 = __ldg((const float4*)(rp + rstep) + 1);
        const float4 x2 = __ldg((const float4*)(rp + 2 * rstep));
        const float4 y2 = __ldg((const float4*)(rp + 2 * rstep) + 1);
        rp += 3 * rstep;

        float d0 = x0.x * q0.x + x0.y * q0.y + x0.z * q0.z + x0.w * q0.w
                 + y0.x * q1.x + y0.y * q1.y + y0.z * q1.z + y0.w * q1.w;
        float d1 = x1.x * q0.x + x1.y * q0.y + x1.z * q0.z + x1.w * q0.w
                 + y1.x * q1.x + y1.y * q1.y + y1.z * q1.z + y1.w * q1.w;
        float d2 = x2.x * q0.x + x2.y * q0.y + x2.z * q0.z + x2.w * q0.w
                 + y2.x * q1.x + y2.y * q1.y + y2.z * q1.z + y2.w * q1.w;
        #pragma unroll
        for (int off = 16; off > 0; off >>= 1) {
            d0 += __shfl_xor_sync(0xffffffffu, d0, off);
            d1 += __shfl_xor_sync(0xffffffffu, d1, off);
            d2 += __shfl_xor_sync(0xffffffffu, d2, off);
        }

        float p0, p1, p2;
        if (uniform) {
            p0 = p1 = p2 = 1.0f;
        } else {
            const float s0 = 1.0f / (1.0f + __expf(-(d0 + b256)));
            const float s1 = 1.0f / (1.0f + __expf(-(d1 + b256)));
            const float s2 = 1.0f / (1.0f + __expf(-(d2 + b256)));
            p0 = __expf(s0 * 0.0625f - 0.0625f);
            p1 = __expf(s1 * 0.0625f - 0.0625f);
            p2 = __expf(s2 * 0.0625f - 0.0625f);
        }

        Z += p0 + p1 + p2;
        c0 += p0 * x0.x + p1 * x1.x + p2 * x2.x;
        c1 += p0 * x0.y + p1 * x1.y + p2 * x2.y;
        c2 += p0 * x0.z + p1 * x1.z + p2 * x2.z;
        c3 += p0 * x0.w + p1 * x1.w + p2 * x2.w;
        c4 += p0 * y0.x + p1 * y1.x + p2 * y2.x;
        c5 += p0 * y0.y + p1 * y1.y + p2 * y2.y;
        c6 += p0 * y0.z + p1 * y1.z + p2 * y2.z;
        c7 += p0 * y0.w + p1 * y1.w + p2 * y2.w;
    }
    #pragma unroll 1
    for (; i < nit; i++) {
        const float4 x0 = __ldg((const float4*)rp);
        const float4 y0 = __ldg((const float4*)rp + 1);
        rp += rstep;
        float d0 = x0.x * q0.x + x0.y * q0.y + x0.z * q0.z + x0.w * q0.w
                 + y0.x * q1.x + y0.y * q1.y + y0.z * q1.z + y0.w * q1.w;
        #pragma unroll
        for (int off = 16; off > 0; off >>= 1)
            d0 += __shfl_xor_sync(0xffffffffu, d0, off);
        float p0;
        if (uniform) {
            p0 = 1.0f;
        } else {
            const float s0 = 1.0f / (1.0f + __expf(-(d0 + b256)));
            p0 = __expf(s0 * 0.0625f - 0.0625f);
        }
        Z += p0;
        c0 += p0 * x0.x; c1 += p0 * x0.y; c2 += p0 * x0.z; c3 += p0 * x0.w;
        c4 += p0 * y0.x; c5 += p0 * y0.y; c6 += p0 * y0.z; c7 += p0 * y0.w;
    }

    if (lane == 0) sZ[w] = Z;   // Z identical across lanes after butterfly
    const int d = lane * 8;
    sctx[w][d + 0] = c0; sctx[w][d + 1] = c1;
    sctx[w][d + 2] = c2; sctx[w][d + 3] = c3;
    sctx[w][d + 4] = c4; sctx[w][d + 5] = c5;
    sctx[w][d + 6] = c6; sctx[w][d + 7] = c7;
    __syncthreads();

    float zt = 0.0f;
    #pragma unroll
    for (int ww = 0; ww < 8; ww++) zt += sZ[ww];
    float c = 0.0f;
    #pragma unroll
    for (int ww = 0; ww < 8; ww++) c += sctx[ww][tid];

    g_CTX[(size_t)b * DSZ + tid] = c / zt;
}

// ---------------------------------------------------------------------------
extern "C" void kernel_launch(void* const* d_in, const int* in_sizes, int n_in,
                              void* d_out, int out_size)
{
    const float* q      = (const float*)d_in[0];   // [2048, 1, 256]
    const float* k      = (const float*)d_in[1];   // [2048, 200, 256]
    // d_in[2] = v: unused (reference derives both score and value paths from k)
    const int*   klen   = (const int*)d_in[3];     // [2048, 1]
    const float* Wq     = (const float*)d_in[4];   // [256, 256]
    const float* Wk     = (const float*)d_in[5];   // [256, 256]
    const float* Wv     = (const float*)d_in[6];   // [256, 256]
    const float* bias   = (const float*)d_in[7];   // [1]
    float* out = (float*)d_out;                    // [2048, 1, 256]

    // 1) M = Wq @ Wk^T
    wmat_kernel<<<256, 256>>>(Wq, Wk);
    // 2) QK = q @ M
    qk_gemm_kernel<<<dim3(BSZ / GM_BM, DSZ / GM_BN), 128>>>(q);
    // 3) attention in k-space (reads only valid rows)
    attn_kernel<<<BSZ, 256>>>(k, klen, bias);
    // 4) out = CTX @ Wv
    out_gemm_kernel<<<dim3(BSZ / GM_BM, DSZ / GM_BN), 128>>>(Wv, out);
}

// round 14
// speedup vs baseline: 1.7225x; 1.2171x over previous
#include <cuda_runtime.h>

#define BSZ 2048
#define LSZ 200
#define DSZ 256

// Scratch (device globals — no allocation allowed).
__device__ float g_M[DSZ * DSZ];     // M = W_query @ W_key^T
__device__ float g_QK[BSZ * DSZ];    // q @ M
__device__ float g_CTX[BSZ * DSZ];   // softmax-weighted sum of k rows

// ---------------------------------------------------------------------------
// g_M[i][j] = Wq[i,:] . Wk[j,:]
// grid = 256 CTAs (one per output row i), 8 warps, warp w covers 32 cols.
// ---------------------------------------------------------------------------
__global__ void wmat_kernel(const float* __restrict__ Wq,
                            const float* __restrict__ Wk)
{
    const int i = blockIdx.x;
    const int w = threadIdx.x >> 5;
    const int lane = threadIdx.x & 31;

    const float4* ap = (const float4*)(Wq + i * 256 + lane * 8);
    const float4 a0 = ap[0];
    const float4 a1 = ap[1];

    float res = 0.0f;
    #pragma unroll 4
    for (int jj = 0; jj < 32; jj++) {
        const int j = w * 32 + jj;
        const float4* bp = (const float4*)(Wk + j * 256 + lane * 8);
        const float4 b0 = __ldg(bp);
        const float4 b1 = __ldg(bp + 1);
        float d = a0.x * b0.x + a0.y * b0.y + a0.z * b0.z + a0.w * b0.w
                + a1.x * b1.x + a1.y * b1.y + a1.z * b1.z + a1.w * b1.w;
        #pragma unroll
        for (int off = 16; off > 0; off >>= 1)
            d += __shfl_xor_sync(0xffffffffu, d, off);
        if (lane == jj) res = d;
    }
    g_M[i * 256 + w * 32 + lane] = res;
}

// ---------------------------------------------------------------------------
// Double-buffered tiled GEMM: C[2048,256] = A[2048,256] @ B[256,256]
// BM=32, BN=64, BK=32, 256 threads, micro 2x4, grid (64,4)=256 CTAs
// (64K threads chip-wide, ~14 warps/SM -> barrier/LDS latency hidden).
// Per warp per kk-step: A = 2 unique float2 (broadcast), B = 16 unique
// float4 -> 3 crossbar cycles vs 16 FFMA issue cycles: FFMA-bound.
// ---------------------------------------------------------------------------
#define GM_BM 32
#define GM_BN 64
#define GM_BK 32
#define GM_PAD 34   // As row stride in floats (136B, 8B-aligned for float2)

__device__ __forceinline__ void tgemm_body(const float* __restrict__ A,
                                           const float* __restrict__ B,
                                           float* __restrict__ C)
{
    __shared__ float As[2][GM_BK][GM_PAD];   // [k][m], transposed
    __shared__ float Bs[2][GM_BK][GM_BN];    // [k][n]

    const int tid = threadIdx.x;
    const int row0 = blockIdx.x * GM_BM;
    const int col0 = blockIdx.y * GM_BN;

    // global load mapping (256 threads)
    const int ar = tid >> 3;              // 0..31 (A row)
    const int ak = (tid & 7) * 4;         // 0..28 (A k-offset, float4)
    const int bk = tid >> 4;              // 0..15 (B k base; +16 for 2nd)
    const int bc = (tid & 15) * 4;        // 0..60 (B col, float4)

    const float* Ap = A + (size_t)(row0 + ar) * DSZ + ak;
    const float* Bp = B + (size_t)bk * DSZ + col0 + bc;

    // compute mapping: 2 rows x 4 cols per thread
    const int ty = tid >> 4;              // 0..15 -> rows ty*2, ty*2+1
    const int tx = tid & 15;              // 0..15 -> cols tx*4..tx*4+3

    float4 acc0 = {0.f,0.f,0.f,0.f};
    float4 acc1 = {0.f,0.f,0.f,0.f};

    // ---- preload chunk 0 into buffer 0
    float4 a0 = __ldg((const float4*)Ap);
    float4 b0 = __ldg((const float4*)Bp);
    float4 b1 = __ldg((const float4*)(Bp + (size_t)16 * DSZ));

    As[0][ak + 0][ar] = a0.x; As[0][ak + 1][ar] = a0.y;
    As[0][ak + 2][ar] = a0.z; As[0][ak + 3][ar] = a0.w;
    *(float4*)&Bs[0][bk][bc]      = b0;
    *(float4*)&Bs[0][bk + 16][bc] = b1;
    __syncthreads();

    int buf = 0;
    #pragma unroll 1
    for (int c = 0; c < DSZ / GM_BK; c++) {
        const bool more = (c + 1 < DSZ / GM_BK);
        if (more) {
            const float* Ap2 = Ap + (c + 1) * GM_BK;
            const float* Bp2 = Bp + (size_t)(c + 1) * GM_BK * DSZ;
            a0 = __ldg((const float4*)Ap2);
            b0 = __ldg((const float4*)Bp2);
            b1 = __ldg((const float4*)(Bp2 + (size_t)16 * DSZ));
        }

        #pragma unroll
        for (int kk = 0; kk < GM_BK; kk++) {
            const float2 av = *(const float2*)&As[buf][kk][ty * 2];
            const float4 bv = *(const float4*)&Bs[buf][kk][tx * 4];
            acc0.x += av.x * bv.x; acc0.y += av.x * bv.y;
            acc0.z += av.x * bv.z; acc0.w += av.x * bv.w;
            acc1.x += av.y * bv.x; acc1.y += av.y * bv.y;
            acc1.z += av.y * bv.z; acc1.w += av.y * bv.w;
        }

        if (more) {
            const int nb = buf ^ 1;       // freed by the previous barrier
            As[nb][ak + 0][ar] = a0.x; As[nb][ak + 1][ar] = a0.y;
            As[nb][ak + 2][ar] = a0.z; As[nb][ak + 3][ar] = a0.w;
            *(float4*)&Bs[nb][bk][bc]      = b0;
            *(float4*)&Bs[nb][bk + 16][bc] = b1;
        }
        __syncthreads();
        buf ^= 1;
    }

    float* Cp = C + (size_t)(row0 + ty * 2) * DSZ + col0 + tx * 4;
    *(float4*)(Cp)       = acc0;
    *(float4*)(Cp + DSZ) = acc1;
}

// QK = q @ g_M
__global__ void __launch_bounds__(256)
qk_gemm_kernel(const float* __restrict__ q)
{
    tgemm_body(q, g_M, g_QK);
}

// out = g_CTX @ Wv
__global__ void __launch_bounds__(256)
out_gemm_kernel(const float* __restrict__ Wv,
                float* __restrict__ out)
{
    tgemm_body(g_CTX, Wv, out);
}

// ---------------------------------------------------------------------------
// Attention in k-space. One CTA per batch (grid 2048, ~3.5 waves -> HW
// load-balancing over variable len). Reads ONLY the first nrows rows:
// masked rows have p == exp(PAD/16 - 1/16) == +0.0f exactly -> contribute
// nothing to Z or CTX. len==0 -> all-PAD -> uniform weights over 200 rows.
// Fixed-max softmax is exact (valid logits = sigmoid/16 in (0, 1/16]).
// Mainloop: 3 rows per outer step -> 6 LDG.128 in flight per warp.
// ---------------------------------------------------------------------------
__global__ void __launch_bounds__(256, 4)
attn_kernel(const float* __restrict__ K,
            const int* __restrict__ keys_length,
            const float* __restrict__ bias)
{
    __shared__ float sZ[8];
    __shared__ float sctx[8][DSZ];

    const int tid = threadIdx.x;
    const int w = tid >> 5;
    const int lane = tid & 31;
    const int b = blockIdx.x;

    const float* kb = K + (size_t)b * LSZ * DSZ;
    const float4* qkp = (const float4*)(g_QK + (size_t)b * DSZ + lane * 8);
    const float4 q0 = qkp[0];
    const float4 q1 = qkp[1];

    const int len = keys_length[b];
    const bool uniform = (len == 0);
    const int nrows = uniform ? LSZ : len;
    const float b256 = bias[0] * 256.0f;

    // warp w owns rows l = w, w+8, w+16, ...
    const int nit = (nrows > w) ? ((nrows - w + 7) >> 3) : 0;
    const float* rp = kb + (size_t)w * DSZ + lane * 8;
    const size_t rstep = (size_t)8 * DSZ;

    float Z = 0.0f;
    float c0 = 0.f, c1 = 0.f, c2 = 0.f, c3 = 0.f;
    float c4 = 0.f, c5 = 0.f, c6 = 0.f, c7 = 0.f;

    int i = 0;
    #pragma unroll 1
    for (; i + 3 <= nit; i += 3) {
        const float4 x0 = __ldg((const float4*)rp);
        const float4 y0 = __ldg((const float4*)rp + 1);
        const float4 x1 = __ldg((const float4*)(rp + rstep));
        const float4 y1 = __ldg((const float4*)(rp + rstep) + 1);
        const float4 x2 = __ldg((const float4*)(rp + 2 * rstep));
        const float4 y2 = __ldg((const float4*)(rp + 2 * rstep) + 1);
        rp += 3 * rstep;

        float d0 = x0.x * q0.x + x0.y * q0.y + x0.z * q0.z + x0.w * q0.w
                 + y0.x * q1.x + y0.y * q1.y + y0.z * q1.z + y0.w * q1.w;
        float d1 = x1.x * q0.x + x1.y * q0.y + x1.z * q0.z + x1.w * q0.w
                 + y1.x * q1.x + y1.y * q1.y + y1.z * q1.z + y1.w * q1.w;
        float d2 = x2.x * q0.x + x2.y * q0.y + x2.z * q0.z + x2.w * q0.w
                 + y2.x * q1.x + y2.y * q1.y + y2.z * q1.z + y2.w * q1.w;
        #pragma unroll
        for (int off = 16; off > 0; off >>= 1) {
            d0 += __shfl_xor_sync(0xffffffffu, d0, off);
            d1 += __shfl_xor_sync(0xffffffffu, d1, off);
            d2 += __shfl_xor_sync(0xffffffffu, d2, off);
        }

        float p0, p1, p2;
        if (uniform) {
            p0 = p1 = p2 = 1.0f;
        } else {
            const float s0 = 1.0f / (1.0f + __expf(-(d0 + b256)));
            const float s1 = 1.0f / (1.0f + __expf(-(d1 + b256)));
            const float s2 = 1.0f / (1.0f + __expf(-(d2 + b256)));
            p0 = __expf(s0 * 0.0625f - 0.0625f);
            p1 = __expf(s1 * 0.0625f - 0.0625f);
            p2 = __expf(s2 * 0.0625f - 0.0625f);
        }

        Z += p0 + p1 + p2;
        c0 += p0 * x0.x + p1 * x1.x + p2 * x2.x;
        c1 += p0 * x0.y + p1 * x1.y + p2 * x2.y;
        c2 += p0 * x0.z + p1 * x1.z + p2 * x2.z;
        c3 += p0 * x0.w + p1 * x1.w + p2 * x2.w;
        c4 += p0 * y0.x + p1 * y1.x + p2 * y2.x;
        c5 += p0 * y0.y + p1 * y1.y + p2 * y2.y;
        c6 += p0 * y0.z + p1 * y1.z + p2 * y2.z;
        c7 += p0 * y0.w + p1 * y1.w + p2 * y2.w;
    }
    #pragma unroll 1
    for (; i < nit; i++) {
        const float4 x0 = __ldg((const float4*)rp);
        const float4 y0 = __ldg((const float4*)rp + 1);
        rp += rstep;
        float d0 = x0.x * q0.x + x0.y * q0.y + x0.z * q0.z + x0.w * q0.w
                 + y0.x * q1.x + y0.y * q1.y + y0.z * q1.z + y0.w * q1.w;
        #pragma unroll
        for (int off = 16; off > 0; off >>= 1)
            d0 += __shfl_xor_sync(0xffffffffu, d0, off);
        float p0;
        if (uniform) {
            p0 = 1.0f;
        } else {
            const float s0 = 1.0f / (1.0f + __expf(-(d0 + b256)));
            p0 = __expf(s0 * 0.0625f - 0.0625f);
        }
        Z += p0;
        c0 += p0 * x0.x; c1 += p0 * x0.y; c2 += p0 * x0.z; c3 += p0 * x0.w;
        c4 += p0 * y0.x; c5 += p0 * y0.y; c6 += p0 * y0.z; c7 += p0 * y0.w;
    }

    if (lane == 0) sZ[w] = Z;   // Z identical across lanes after butterfly
    const int d = lane * 8;
    sctx[w][d + 0] = c0; sctx[w][d + 1] = c1;
    sctx[w][d + 2] = c2; sctx[w][d + 3] = c3;
    sctx[w][d + 4] = c4; sctx[w][d + 5] = c5;
    sctx[w][d + 6] = c6; sctx[w][d + 7] = c7;
    __syncthreads();

    float zt = 0.0f;
    #pragma unroll
    for (int ww = 0; ww < 8; ww++) zt += sZ[ww];
    float c = 0.0f;
    #pragma unroll
    for (int ww = 0; ww < 8; ww++) c += sctx[ww][tid];

    g_CTX[(size_t)b * DSZ + tid] = c / zt;
}

// ---------------------------------------------------------------------------
extern "C" void kernel_launch(void* const* d_in, const int* in_sizes, int n_in,
                              void* d_out, int out_size)
{
    const float* q      = (const float*)d_in[0];   // [2048, 1, 256]
    const float* k      = (const float*)d_in[1];   // [2048, 200, 256]
    // d_in[2] = v: unused (reference derives both score and value paths from k)
    const int*   klen   = (const int*)d_in[3];     // [2048, 1]
    const float* Wq     = (const float*)d_in[4];   // [256, 256]
    const float* Wk     = (const float*)d_in[5];   // [256, 256]
    const float* Wv     = (const float*)d_in[6];   // [256, 256]
    const float* bias   = (const float*)d_in[7];   // [1]
    float* out = (float*)d_out;                    // [2048, 1, 256]

    // 1) M = Wq @ Wk^T
    wmat_kernel<<<256, 256>>>(Wq, Wk);
    // 2) QK = q @ M
    qk_gemm_kernel<<<dim3(BSZ / GM_BM, DSZ / GM_BN), 256>>>(q);
    // 3) attention in k-space (reads only valid rows)
    attn_kernel<<<BSZ, 256>>>(k, klen, bias);
    // 4) out = CTX @ Wv
    out_gemm_kernel<<<dim3(BSZ / GM_BM, DSZ / GM_BN), 256>>>(Wv, out);
}